// round 2
// baseline (speedup 1.0000x reference)
#include <cuda_runtime.h>

#define D_MODEL 1024
#define NUM_HEADS 16
#define HEAD_DIM 64
#define BATCH 4
#define SEQ 2048
#define MTOT (BATCH*SEQ)

// ---------------- scratch (device globals: no allocs allowed) ----------------
__device__ float g_q[(size_t)MTOT * D_MODEL];
__device__ float g_k[(size_t)MTOT * D_MODEL];
__device__ float g_v[(size_t)MTOT * D_MODEL];
__device__ float g_attn[(size_t)MTOT * D_MODEL];

// ---------------- GEMM: C[M,N] = A[M,K] @ W[K,N] + bias[N] ------------------
#define BM 64
#define BN 64
#define BK 16

__global__ __launch_bounds__(256)
void gemm_bias_kernel(const float* __restrict__ A,
                      const float* __restrict__ W,
                      const float* __restrict__ bias,
                      float* __restrict__ C,
                      int M, int N, int K)
{
    __shared__ float As[BK][BM];   // A tile stored transposed: As[k][m]
    __shared__ float Bs[BK][BN];   // Bs[k][n]

    const int tid = threadIdx.x;
    const int tx = tid & 15;       // 0..15 -> N microtile
    const int ty = tid >> 4;       // 0..15 -> M microtile
    const int row0 = blockIdx.y * BM;
    const int col0 = blockIdx.x * BN;

    // A-tile load: thread loads A[row0 + tid/4][k0 + (tid%4)*4 .. +3]
    const int la_r = tid >> 2;          // 0..63
    const int la_k = (tid & 3) << 2;    // 0,4,8,12
    // B-tile load: thread loads W[k0 + tid/16][col0 + (tid%16)*4 .. +3]
    const int lb_k = tid >> 4;          // 0..15
    const int lb_c = (tid & 15) << 2;   // 0..60

    float acc[4][4];
#pragma unroll
    for (int i = 0; i < 4; ++i)
#pragma unroll
        for (int j = 0; j < 4; ++j) acc[i][j] = 0.f;

    for (int k0 = 0; k0 < K; k0 += BK) {
        float4 a4 = *(const float4*)&A[(size_t)(row0 + la_r) * K + k0 + la_k];
        float4 b4 = *(const float4*)&W[(size_t)(k0 + lb_k) * N + col0 + lb_c];

        __syncthreads();   // protect previous iteration's smem reads
        As[la_k + 0][la_r] = a4.x;
        As[la_k + 1][la_r] = a4.y;
        As[la_k + 2][la_r] = a4.z;
        As[la_k + 3][la_r] = a4.w;
        *(float4*)&Bs[lb_k][lb_c] = b4;
        __syncthreads();

#pragma unroll
        for (int kk = 0; kk < BK; ++kk) {
            float ar[4], br[4];
            *(float4*)ar = *(const float4*)&As[kk][ty << 2];
            *(float4*)br = *(const float4*)&Bs[kk][tx << 2];
#pragma unroll
            for (int i = 0; i < 4; ++i)
#pragma unroll
                for (int j = 0; j < 4; ++j)
                    acc[i][j] += ar[i] * br[j];
        }
    }

    float bb[4];
    *(float4*)bb = *(const float4*)&bias[col0 + (tx << 2)];
#pragma unroll
    for (int i = 0; i < 4; ++i) {
        int row = row0 + (ty << 2) + i;
        float4 out;
        out.x = acc[i][0] + bb[0];
        out.y = acc[i][1] + bb[1];
        out.z = acc[i][2] + bb[2];
        out.w = acc[i][3] + bb[3];
        *(float4*)&C[(size_t)row * N + col0 + (tx << 2)] = out;
    }
}

// ---------------- Flash attention (fp32, online softmax) --------------------
// One block = 128 threads = BR=128 query rows of one (b,h). Thread r owns row r.
// Q stored TRANSPOSED in smem: qs[d][r]  -> per-lane reads conflict-free.
// K/V tiles [BC=32][64] read broadcast (same address across all lanes).
#define BR 128
#define BC 32

__global__ __launch_bounds__(128)
void flash_attn_kernel(const float* __restrict__ Q,
                       const float* __restrict__ Km,
                       const float* __restrict__ V,
                       float* __restrict__ O)
{
    __shared__ float qs[HEAD_DIM][BR];        // 64*128*4 = 32768 B
    __shared__ float ks[BC][HEAD_DIM];        //  8192 B
    __shared__ float vs[BC][HEAD_DIM];        //  8192 B  (total = 48 KB exactly)

    const int t  = threadIdx.x;
    const int q0 = blockIdx.x * BR;
    const int bh = blockIdx.y;
    const int b  = bh / NUM_HEADS;
    const int h  = bh % NUM_HEADS;
    const size_t base = (size_t)b * SEQ * D_MODEL + (size_t)h * HEAD_DIM;

    // Load my Q row, store transposed (column writes: bank = t%32, conflict-free)
    {
        const float* qg = Q + base + (size_t)(q0 + t) * D_MODEL;
#pragma unroll
        for (int d = 0; d < HEAD_DIM; d += 4) {
            float4 v4 = *(const float4*)&qg[d];
            qs[d + 0][t] = v4.x;
            qs[d + 1][t] = v4.y;
            qs[d + 2][t] = v4.z;
            qs[d + 3][t] = v4.w;
        }
    }

    float o[HEAD_DIM];
#pragma unroll
    for (int d = 0; d < HEAD_DIM; ++d) o[d] = 0.f;
    float mrun = -1e30f;
    float lrun = 0.f;
    const float scale = 0.125f;  // 1/sqrt(64)

    __syncthreads();

    for (int c0 = 0; c0 < SEQ; c0 += BC) {
        __syncthreads();  // protect previous iteration's ks/vs reads
        // Load K,V tiles: 32x64 floats each; 128 threads * 4 float4, coalesced
#pragma unroll
        for (int i = 0; i < 4; ++i) {
            int f  = t + i * 128;        // float4 index 0..511
            int rr = f >> 4;             // tile row 0..31
            int cc = (f & 15) << 2;      // col 0..60
            size_t goff = base + (size_t)(c0 + rr) * D_MODEL + cc;
            *(float4*)&ks[rr][cc] = *(const float4*)&Km[goff];
            *(float4*)&vs[rr][cc] = *(const float4*)&V[goff];
        }
        __syncthreads();

        // s[c] = q_row . k_row(c)
        float s[BC];
#pragma unroll
        for (int c = 0; c < BC; ++c) s[c] = 0.f;
#pragma unroll
        for (int d = 0; d < HEAD_DIM; d += 4) {
            float q0r = qs[d + 0][t];
            float q1r = qs[d + 1][t];
            float q2r = qs[d + 2][t];
            float q3r = qs[d + 3][t];
#pragma unroll
            for (int c = 0; c < BC; ++c) {
                float k4[4];
                *(float4*)k4 = *(const float4*)&ks[c][d];
                s[c] += q0r * k4[0] + q1r * k4[1] + q2r * k4[2] + q3r * k4[3];
            }
        }

        // online softmax (entirely thread-local: thread owns the whole row)
        float mnew = mrun;
#pragma unroll
        for (int c = 0; c < BC; ++c) {
            s[c] *= scale;
            mnew = fmaxf(mnew, s[c]);
        }
        float corr = __expf(mrun - mnew);
        mrun = mnew;
        lrun *= corr;
#pragma unroll
        for (int c = 0; c < BC; ++c) {
            float p = __expf(s[c] - mnew);
            s[c] = p;
            lrun += p;
        }
#pragma unroll
        for (int d = 0; d < HEAD_DIM; ++d) o[d] *= corr;

        // o += P @ V
#pragma unroll
        for (int c = 0; c < BC; ++c) {
            float p = s[c];
#pragma unroll
            for (int d = 0; d < HEAD_DIM; d += 4) {
                float v4[4];
                *(float4*)v4 = *(const float4*)&vs[c][d];
                o[d + 0] += p * v4[0];
                o[d + 1] += p * v4[1];
                o[d + 2] += p * v4[2];
                o[d + 3] += p * v4[3];
            }
        }
    }

    const float inv = 1.f / lrun;
    float* og = O + base + (size_t)(q0 + t) * D_MODEL;
#pragma unroll
    for (int d = 0; d < HEAD_DIM; d += 4) {
        float4 v4;
        v4.x = o[d + 0] * inv;
        v4.y = o[d + 1] * inv;
        v4.z = o[d + 2] * inv;
        v4.w = o[d + 3] * inv;
        *(float4*)&og[d] = v4;
    }
}

// ---------------- launch ----------------------------------------------------
extern "C" void kernel_launch(void* const* d_in, const int* in_sizes, int n_in,
                              void* d_out, int out_size)
{
    const float* query = (const float*)d_in[0];
    const float* key   = (const float*)d_in[1];
    const float* value = (const float*)d_in[2];
    const float* Wq    = (const float*)d_in[3];
    const float* bq    = (const float*)d_in[4];
    const float* Wk    = (const float*)d_in[5];
    const float* bk    = (const float*)d_in[6];
    const float* Wv    = (const float*)d_in[7];
    const float* bv    = (const float*)d_in[8];
    const float* Wo    = (const float*)d_in[9];
    const float* bo    = (const float*)d_in[10];
    float* out = (float*)d_out;

    float *pq, *pk, *pv, *pa;
    cudaGetSymbolAddress((void**)&pq, g_q);
    cudaGetSymbolAddress((void**)&pk, g_k);
    cudaGetSymbolAddress((void**)&pv, g_v);
    cudaGetSymbolAddress((void**)&pa, g_attn);

    dim3 gblk(D_MODEL / BN, MTOT / BM);   // 16 x 128
    dim3 gthr(256);

    gemm_bias_kernel<<<gblk, gthr>>>(query, Wq, bq, pq, MTOT, D_MODEL, D_MODEL);
    gemm_bias_kernel<<<gblk, gthr>>>(key,   Wk, bk, pk, MTOT, D_MODEL, D_MODEL);
    gemm_bias_kernel<<<gblk, gthr>>>(value, Wv, bv, pv, MTOT, D_MODEL, D_MODEL);

    dim3 ablk(SEQ / BR, BATCH * NUM_HEADS);  // 16 x 64
    flash_attn_kernel<<<ablk, 128>>>(pq, pk, pv, pa);

    gemm_bias_kernel<<<gblk, gthr>>>(pa, Wo, bo, out, MTOT, D_MODEL, D_MODEL);
}

// round 3
// speedup vs baseline: 2.1843x; 2.1843x over previous
#include <cuda_runtime.h>
#include <cstdint>

#define D_MODEL 1024
#define NUM_HEADS 16
#define HEAD_DIM 64
#define BATCH 4
#define SEQ 2048
#define MTOT (BATCH*SEQ)

// ---------------- scratch (device globals: no allocs allowed) ----------------
__device__ float g_q[(size_t)MTOT * D_MODEL];
__device__ float g_k[(size_t)MTOT * D_MODEL];
__device__ float g_v[(size_t)MTOT * D_MODEL];
__device__ float g_attn[(size_t)MTOT * D_MODEL];

// ---------------- helpers ----------------------------------------------------
__device__ __forceinline__ uint32_t f2tf32(float x) {
    uint32_t r;
    asm("cvt.rna.tf32.f32 %0, %1;" : "=r"(r) : "f"(x));
    return r;
}

#define LDMATRIX_X4(R0, R1, R2, R3, addr)                                       \
    asm volatile("ldmatrix.sync.aligned.m8n8.x4.shared.b16 {%0,%1,%2,%3}, [%4];" \
                 : "=r"(R0), "=r"(R1), "=r"(R2), "=r"(R3) : "r"(addr))

#define MMA_TF32(C0, C1, C2, C3, A0, A1, A2, A3, B0, B1)                        \
    asm volatile("mma.sync.aligned.m16n8k8.row.col.f32.tf32.tf32.f32 "          \
                 "{%0,%1,%2,%3},{%4,%5,%6,%7},{%8,%9},{%0,%1,%2,%3};"           \
                 : "+f"(C0), "+f"(C1), "+f"(C2), "+f"(C3)                       \
                 : "r"(A0), "r"(A1), "r"(A2), "r"(A3), "r"(B0), "r"(B1))

// ---------------- TF32 tensor-core GEMM: C = A[M,K] @ W[K,N] + bias ----------
// BM=128, BN=64, BK=16. 8 warps in 4(m) x 2(n); warp tile 32x32.
// As[m][k] stride 20 (ldmatrix-conflict-free), Ws[n][k] stride 20 (W transposed).
#define GBM 128
#define GBN 64
#define GBK 16
#define SA 20
#define SW 20

__global__ __launch_bounds__(256, 2)
void gemm_tf32_kernel(const float* __restrict__ A,
                      const float* __restrict__ W,
                      const float* __restrict__ bias,
                      float* __restrict__ C,
                      int M, int N, int K)
{
    __shared__ float As[GBM * SA];
    __shared__ float Ws[GBN * SW];

    const int tid  = threadIdx.x;
    const int lane = tid & 31;
    const int wid  = tid >> 5;
    const int wm   = wid >> 1;          // 0..3 (m)
    const int wn   = wid & 1;           // 0..1 (n)
    const int row0 = blockIdx.y * GBM;
    const int col0 = blockIdx.x * GBN;

    // A global-load mapping: rows ar and ar+64, k-quad akq
    const int ar  = tid >> 2;           // 0..63
    const int akq = (tid & 3) << 2;     // 0,4,8,12
    // W global-load mapping: coalesced along n, 4 strided k rows; store transposed
    const int wnx = tid & 63;           // n within tile
    const int wkg = (tid >> 6) << 2;    // 0,4,8,12

    // ldmatrix per-lane smem addresses
    const int lj = lane >> 3;           // matrix index 0..3
    const int lr = lane & 7;            // row within matrix
    const uint32_t as_base = (uint32_t)__cvta_generic_to_shared(As);
    const uint32_t ws_base = (uint32_t)__cvta_generic_to_shared(Ws);
    uint32_t a_addr[2], b_addr[2];
#pragma unroll
    for (int i = 0; i < 2; ++i)
        a_addr[i] = as_base + (((wm * 32 + i * 16 + lr + 8 * (lj & 1)) * SA
                               + 4 * (lj >> 1)) << 2);
#pragma unroll
    for (int t = 0; t < 2; ++t)
        b_addr[t] = ws_base + (((wn * 32 + t * 16 + lr + 8 * (lj >> 1)) * SW
                               + 4 * (lj & 1)) << 2);

    float acc[2][4][4];
#pragma unroll
    for (int i = 0; i < 2; ++i)
#pragma unroll
        for (int j = 0; j < 4; ++j)
#pragma unroll
            for (int e = 0; e < 4; ++e) acc[i][j][e] = 0.f;

    const float* Ap0 = A + (size_t)(row0 + ar) * K + akq;
    const float* Ap1 = A + (size_t)(row0 + 64 + ar) * K + akq;
    const float* Wp  = W + (size_t)wkg * N + col0 + wnx;

    float4 pa0, pa1;
    float pw0, pw1, pw2, pw3;

    // prologue: load k0 = 0
    pa0 = *(const float4*)Ap0;
    pa1 = *(const float4*)Ap1;
    pw0 = Wp[0]; pw1 = Wp[(size_t)N]; pw2 = Wp[(size_t)2 * N]; pw3 = Wp[(size_t)3 * N];

    // store tile 0 (with tf32 rounding)
    {
        float4 s0, s1, sw;
        s0.x = __uint_as_float(f2tf32(pa0.x)); s0.y = __uint_as_float(f2tf32(pa0.y));
        s0.z = __uint_as_float(f2tf32(pa0.z)); s0.w = __uint_as_float(f2tf32(pa0.w));
        s1.x = __uint_as_float(f2tf32(pa1.x)); s1.y = __uint_as_float(f2tf32(pa1.y));
        s1.z = __uint_as_float(f2tf32(pa1.z)); s1.w = __uint_as_float(f2tf32(pa1.w));
        sw.x = __uint_as_float(f2tf32(pw0));   sw.y = __uint_as_float(f2tf32(pw1));
        sw.z = __uint_as_float(f2tf32(pw2));   sw.w = __uint_as_float(f2tf32(pw3));
        *(float4*)&As[ar * SA + akq]        = s0;
        *(float4*)&As[(64 + ar) * SA + akq] = s1;
        *(float4*)&Ws[wnx * SW + wkg]       = sw;
    }
    __syncthreads();

    for (int k0 = 0; k0 < K; k0 += GBK) {
        const bool has_next = (k0 + GBK) < K;
        if (has_next) {
            pa0 = *(const float4*)(Ap0 + k0 + GBK);
            pa1 = *(const float4*)(Ap1 + k0 + GBK);
            const float* wp = Wp + (size_t)(k0 + GBK) * N;
            pw0 = wp[0]; pw1 = wp[(size_t)N]; pw2 = wp[(size_t)2 * N]; pw3 = wp[(size_t)3 * N];
        }

#pragma unroll
        for (int ks = 0; ks < GBK; ks += 8) {
            uint32_t a[2][4], bq[2][4];
            LDMATRIX_X4(a[0][0], a[0][1], a[0][2], a[0][3], a_addr[0] + (ks << 2));
            LDMATRIX_X4(a[1][0], a[1][1], a[1][2], a[1][3], a_addr[1] + (ks << 2));
            LDMATRIX_X4(bq[0][0], bq[0][1], bq[0][2], bq[0][3], b_addr[0] + (ks << 2));
            LDMATRIX_X4(bq[1][0], bq[1][1], bq[1][2], bq[1][3], b_addr[1] + (ks << 2));
#pragma unroll
            for (int i = 0; i < 2; ++i) {
                MMA_TF32(acc[i][0][0], acc[i][0][1], acc[i][0][2], acc[i][0][3],
                         a[i][0], a[i][1], a[i][2], a[i][3], bq[0][0], bq[0][1]);
                MMA_TF32(acc[i][1][0], acc[i][1][1], acc[i][1][2], acc[i][1][3],
                         a[i][0], a[i][1], a[i][2], a[i][3], bq[0][2], bq[0][3]);
                MMA_TF32(acc[i][2][0], acc[i][2][1], acc[i][2][2], acc[i][2][3],
                         a[i][0], a[i][1], a[i][2], a[i][3], bq[1][0], bq[1][1]);
                MMA_TF32(acc[i][3][0], acc[i][3][1], acc[i][3][2], acc[i][3][3],
                         a[i][0], a[i][1], a[i][2], a[i][3], bq[1][2], bq[1][3]);
            }
        }

        __syncthreads();
        if (has_next) {
            float4 s0, s1, sw;
            s0.x = __uint_as_float(f2tf32(pa0.x)); s0.y = __uint_as_float(f2tf32(pa0.y));
            s0.z = __uint_as_float(f2tf32(pa0.z)); s0.w = __uint_as_float(f2tf32(pa0.w));
            s1.x = __uint_as_float(f2tf32(pa1.x)); s1.y = __uint_as_float(f2tf32(pa1.y));
            s1.z = __uint_as_float(f2tf32(pa1.z)); s1.w = __uint_as_float(f2tf32(pa1.w));
            sw.x = __uint_as_float(f2tf32(pw0));   sw.y = __uint_as_float(f2tf32(pw1));
            sw.z = __uint_as_float(f2tf32(pw2));   sw.w = __uint_as_float(f2tf32(pw3));
            *(float4*)&As[ar * SA + akq]        = s0;
            *(float4*)&As[(64 + ar) * SA + akq] = s1;
            *(float4*)&Ws[wnx * SW + wkg]       = sw;
            __syncthreads();
        }
    }

    // epilogue: bias + store (float2 per half-tile)
#pragma unroll
    for (int i = 0; i < 2; ++i) {
        const int r = row0 + wm * 32 + i * 16 + (lane >> 2);
#pragma unroll
        for (int j = 0; j < 4; ++j) {
            const int c = col0 + wn * 32 + j * 8 + ((lane & 3) << 1);
            const float b0 = __ldg(&bias[c]);
            const float b1 = __ldg(&bias[c + 1]);
            float2 v0, v1;
            v0.x = acc[i][j][0] + b0; v0.y = acc[i][j][1] + b1;
            v1.x = acc[i][j][2] + b0; v1.y = acc[i][j][3] + b1;
            *(float2*)&C[(size_t)r * N + c]       = v0;
            *(float2*)&C[(size_t)(r + 8) * N + c] = v1;
        }
    }
}

// ---------------- Flash attention (fp32, online softmax) --------------------
#define BR 128
#define BC 32

__global__ __launch_bounds__(128)
void flash_attn_kernel(const float* __restrict__ Q,
                       const float* __restrict__ Km,
                       const float* __restrict__ V,
                       float* __restrict__ O)
{
    __shared__ float qs[HEAD_DIM][BR];        // 32768 B
    __shared__ float ks[BC][HEAD_DIM];        //  8192 B
    __shared__ float vs[BC][HEAD_DIM];        //  8192 B

    const int t  = threadIdx.x;
    const int q0 = blockIdx.x * BR;
    const int bh = blockIdx.y;
    const int b  = bh / NUM_HEADS;
    const int h  = bh % NUM_HEADS;
    const size_t base = (size_t)b * SEQ * D_MODEL + (size_t)h * HEAD_DIM;

    {
        const float* qg = Q + base + (size_t)(q0 + t) * D_MODEL;
#pragma unroll
        for (int d = 0; d < HEAD_DIM; d += 4) {
            float4 v4 = *(const float4*)&qg[d];
            qs[d + 0][t] = v4.x;
            qs[d + 1][t] = v4.y;
            qs[d + 2][t] = v4.z;
            qs[d + 3][t] = v4.w;
        }
    }

    float o[HEAD_DIM];
#pragma unroll
    for (int d = 0; d < HEAD_DIM; ++d) o[d] = 0.f;
    float mrun = -1e30f;
    float lrun = 0.f;
    const float scale = 0.125f;

    __syncthreads();

    for (int c0 = 0; c0 < SEQ; c0 += BC) {
        __syncthreads();
#pragma unroll
        for (int i = 0; i < 4; ++i) {
            int f  = t + i * 128;
            int rr = f >> 4;
            int cc = (f & 15) << 2;
            size_t goff = base + (size_t)(c0 + rr) * D_MODEL + cc;
            *(float4*)&ks[rr][cc] = *(const float4*)&Km[goff];
            *(float4*)&vs[rr][cc] = *(const float4*)&V[goff];
        }
        __syncthreads();

        float s[BC];
#pragma unroll
        for (int c = 0; c < BC; ++c) s[c] = 0.f;
#pragma unroll
        for (int d = 0; d < HEAD_DIM; d += 4) {
            float q0r = qs[d + 0][t];
            float q1r = qs[d + 1][t];
            float q2r = qs[d + 2][t];
            float q3r = qs[d + 3][t];
#pragma unroll
            for (int c = 0; c < BC; ++c) {
                float k4[4];
                *(float4*)k4 = *(const float4*)&ks[c][d];
                s[c] += q0r * k4[0] + q1r * k4[1] + q2r * k4[2] + q3r * k4[3];
            }
        }

        float mnew = mrun;
#pragma unroll
        for (int c = 0; c < BC; ++c) {
            s[c] *= scale;
            mnew = fmaxf(mnew, s[c]);
        }
        float corr = __expf(mrun - mnew);
        mrun = mnew;
        lrun *= corr;
#pragma unroll
        for (int c = 0; c < BC; ++c) {
            float p = __expf(s[c] - mnew);
            s[c] = p;
            lrun += p;
        }
#pragma unroll
        for (int d = 0; d < HEAD_DIM; ++d) o[d] *= corr;

#pragma unroll
        for (int c = 0; c < BC; ++c) {
            float p = s[c];
#pragma unroll
            for (int d = 0; d < HEAD_DIM; d += 4) {
                float v4[4];
                *(float4*)v4 = *(const float4*)&vs[c][d];
                o[d + 0] += p * v4[0];
                o[d + 1] += p * v4[1];
                o[d + 2] += p * v4[2];
                o[d + 3] += p * v4[3];
            }
        }
    }

    const float inv = 1.f / lrun;
    float* og = O + base + (size_t)(q0 + t) * D_MODEL;
#pragma unroll
    for (int d = 0; d < HEAD_DIM; d += 4) {
        float4 v4;
        v4.x = o[d + 0] * inv;
        v4.y = o[d + 1] * inv;
        v4.z = o[d + 2] * inv;
        v4.w = o[d + 3] * inv;
        *(float4*)&og[d] = v4;
    }
}

// ---------------- launch ----------------------------------------------------
extern "C" void kernel_launch(void* const* d_in, const int* in_sizes, int n_in,
                              void* d_out, int out_size)
{
    const float* query = (const float*)d_in[0];
    const float* key   = (const float*)d_in[1];
    const float* value = (const float*)d_in[2];
    const float* Wq    = (const float*)d_in[3];
    const float* bq    = (const float*)d_in[4];
    const float* Wk    = (const float*)d_in[5];
    const float* bk    = (const float*)d_in[6];
    const float* Wv    = (const float*)d_in[7];
    const float* bv    = (const float*)d_in[8];
    const float* Wo    = (const float*)d_in[9];
    const float* bo    = (const float*)d_in[10];
    float* out = (float*)d_out;

    float *pq, *pk, *pv, *pa;
    cudaGetSymbolAddress((void**)&pq, g_q);
    cudaGetSymbolAddress((void**)&pk, g_k);
    cudaGetSymbolAddress((void**)&pv, g_v);
    cudaGetSymbolAddress((void**)&pa, g_attn);

    dim3 gblk(D_MODEL / GBN, MTOT / GBM);   // 16 x 64
    dim3 gthr(256);

    gemm_tf32_kernel<<<gblk, gthr>>>(query, Wq, bq, pq, MTOT, D_MODEL, D_MODEL);
    gemm_tf32_kernel<<<gblk, gthr>>>(key,   Wk, bk, pk, MTOT, D_MODEL, D_MODEL);
    gemm_tf32_kernel<<<gblk, gthr>>>(value, Wv, bv, pv, MTOT, D_MODEL, D_MODEL);

    dim3 ablk(SEQ / BR, BATCH * NUM_HEADS);  // 16 x 64
    flash_attn_kernel<<<ablk, 128>>>(pq, pk, pv, pa);

    gemm_tf32_kernel<<<gblk, gthr>>>(pa, Wo, bo, out, MTOT, D_MODEL, D_MODEL);
}

// round 4
// speedup vs baseline: 5.1932x; 2.3776x over previous
#include <cuda_runtime.h>
#include <cstdint>

#define D_MODEL 1024
#define NUM_HEADS 16
#define HEAD_DIM 64
#define BATCH 4
#define SEQ 2048
#define MTOT (BATCH*SEQ)

// ---------------- scratch (device globals: no allocs allowed) ----------------
__device__ float g_q[(size_t)MTOT * D_MODEL];
__device__ float g_k[(size_t)MTOT * D_MODEL];
__device__ float g_v[(size_t)MTOT * D_MODEL];
__device__ float g_attn[(size_t)MTOT * D_MODEL];

// ---------------- helpers ----------------------------------------------------
__device__ __forceinline__ uint32_t f2tf32(float x) {
    uint32_t r;
    asm("cvt.rna.tf32.f32 %0, %1;" : "=r"(r) : "f"(x));
    return r;
}
__device__ __forceinline__ float ex2(float x) {
    float y;
    asm("ex2.approx.f32 %0, %1;" : "=f"(y) : "f"(x));
    return y;
}

#define LDMATRIX_X4(R0, R1, R2, R3, addr)                                       \
    asm volatile("ldmatrix.sync.aligned.m8n8.x4.shared.b16 {%0,%1,%2,%3}, [%4];" \
                 : "=r"(R0), "=r"(R1), "=r"(R2), "=r"(R3) : "r"(addr))

#define MMA_TF32(C0, C1, C2, C3, A0, A1, A2, A3, B0, B1)                        \
    asm volatile("mma.sync.aligned.m16n8k8.row.col.f32.tf32.tf32.f32 "          \
                 "{%0,%1,%2,%3},{%4,%5,%6,%7},{%8,%9},{%0,%1,%2,%3};"           \
                 : "+f"(C0), "+f"(C1), "+f"(C2), "+f"(C3)                       \
                 : "r"(A0), "r"(A1), "r"(A2), "r"(A3), "r"(B0), "r"(B1))

// ---------------- TF32 tensor-core GEMM: C = A[M,K] @ W[K,N] + bias ----------
#define GBM 128
#define GBN 64
#define GBK 16
#define SA 20
#define SW 20

__global__ __launch_bounds__(256, 2)
void gemm_tf32_kernel(const float* __restrict__ A,
                      const float* __restrict__ W,
                      const float* __restrict__ bias,
                      float* __restrict__ C,
                      int M, int N, int K)
{
    __shared__ float As[GBM * SA];
    __shared__ float Ws[GBN * SW];

    const int tid  = threadIdx.x;
    const int lane = tid & 31;
    const int wid  = tid >> 5;
    const int wm   = wid >> 1;
    const int wn   = wid & 1;
    const int row0 = blockIdx.y * GBM;
    const int col0 = blockIdx.x * GBN;

    const int ar  = tid >> 2;
    const int akq = (tid & 3) << 2;
    const int wnx = tid & 63;
    const int wkg = (tid >> 6) << 2;

    const int lj = lane >> 3;
    const int lr = lane & 7;
    const uint32_t as_base = (uint32_t)__cvta_generic_to_shared(As);
    const uint32_t ws_base = (uint32_t)__cvta_generic_to_shared(Ws);
    uint32_t a_addr[2], b_addr[2];
#pragma unroll
    for (int i = 0; i < 2; ++i)
        a_addr[i] = as_base + (((wm * 32 + i * 16 + lr + 8 * (lj & 1)) * SA
                               + 4 * (lj >> 1)) << 2);
#pragma unroll
    for (int t = 0; t < 2; ++t)
        b_addr[t] = ws_base + (((wn * 32 + t * 16 + lr + 8 * (lj >> 1)) * SW
                               + 4 * (lj & 1)) << 2);

    float acc[2][4][4];
#pragma unroll
    for (int i = 0; i < 2; ++i)
#pragma unroll
        for (int j = 0; j < 4; ++j)
#pragma unroll
            for (int e = 0; e < 4; ++e) acc[i][j][e] = 0.f;

    const float* Ap0 = A + (size_t)(row0 + ar) * K + akq;
    const float* Ap1 = A + (size_t)(row0 + 64 + ar) * K + akq;
    const float* Wp  = W + (size_t)wkg * N + col0 + wnx;

    float4 pa0, pa1;
    float pw0, pw1, pw2, pw3;

    pa0 = *(const float4*)Ap0;
    pa1 = *(const float4*)Ap1;
    pw0 = Wp[0]; pw1 = Wp[(size_t)N]; pw2 = Wp[(size_t)2 * N]; pw3 = Wp[(size_t)3 * N];

    {
        float4 s0, s1, sw;
        s0.x = __uint_as_float(f2tf32(pa0.x)); s0.y = __uint_as_float(f2tf32(pa0.y));
        s0.z = __uint_as_float(f2tf32(pa0.z)); s0.w = __uint_as_float(f2tf32(pa0.w));
        s1.x = __uint_as_float(f2tf32(pa1.x)); s1.y = __uint_as_float(f2tf32(pa1.y));
        s1.z = __uint_as_float(f2tf32(pa1.z)); s1.w = __uint_as_float(f2tf32(pa1.w));
        sw.x = __uint_as_float(f2tf32(pw0));   sw.y = __uint_as_float(f2tf32(pw1));
        sw.z = __uint_as_float(f2tf32(pw2));   sw.w = __uint_as_float(f2tf32(pw3));
        *(float4*)&As[ar * SA + akq]        = s0;
        *(float4*)&As[(64 + ar) * SA + akq] = s1;
        *(float4*)&Ws[wnx * SW + wkg]       = sw;
    }
    __syncthreads();

    for (int k0 = 0; k0 < K; k0 += GBK) {
        const bool has_next = (k0 + GBK) < K;
        if (has_next) {
            pa0 = *(const float4*)(Ap0 + k0 + GBK);
            pa1 = *(const float4*)(Ap1 + k0 + GBK);
            const float* wp = Wp + (size_t)(k0 + GBK) * N;
            pw0 = wp[0]; pw1 = wp[(size_t)N]; pw2 = wp[(size_t)2 * N]; pw3 = wp[(size_t)3 * N];
        }

#pragma unroll
        for (int ks = 0; ks < GBK; ks += 8) {
            uint32_t a[2][4], bq[2][4];
            LDMATRIX_X4(a[0][0], a[0][1], a[0][2], a[0][3], a_addr[0] + (ks << 2));
            LDMATRIX_X4(a[1][0], a[1][1], a[1][2], a[1][3], a_addr[1] + (ks << 2));
            LDMATRIX_X4(bq[0][0], bq[0][1], bq[0][2], bq[0][3], b_addr[0] + (ks << 2));
            LDMATRIX_X4(bq[1][0], bq[1][1], bq[1][2], bq[1][3], b_addr[1] + (ks << 2));
#pragma unroll
            for (int i = 0; i < 2; ++i) {
                MMA_TF32(acc[i][0][0], acc[i][0][1], acc[i][0][2], acc[i][0][3],
                         a[i][0], a[i][1], a[i][2], a[i][3], bq[0][0], bq[0][1]);
                MMA_TF32(acc[i][1][0], acc[i][1][1], acc[i][1][2], acc[i][1][3],
                         a[i][0], a[i][1], a[i][2], a[i][3], bq[0][2], bq[0][3]);
                MMA_TF32(acc[i][2][0], acc[i][2][1], acc[i][2][2], acc[i][2][3],
                         a[i][0], a[i][1], a[i][2], a[i][3], bq[1][0], bq[1][1]);
                MMA_TF32(acc[i][3][0], acc[i][3][1], acc[i][3][2], acc[i][3][3],
                         a[i][0], a[i][1], a[i][2], a[i][3], bq[1][2], bq[1][3]);
            }
        }

        __syncthreads();
        if (has_next) {
            float4 s0, s1, sw;
            s0.x = __uint_as_float(f2tf32(pa0.x)); s0.y = __uint_as_float(f2tf32(pa0.y));
            s0.z = __uint_as_float(f2tf32(pa0.z)); s0.w = __uint_as_float(f2tf32(pa0.w));
            s1.x = __uint_as_float(f2tf32(pa1.x)); s1.y = __uint_as_float(f2tf32(pa1.y));
            s1.z = __uint_as_float(f2tf32(pa1.z)); s1.w = __uint_as_float(f2tf32(pa1.w));
            sw.x = __uint_as_float(f2tf32(pw0));   sw.y = __uint_as_float(f2tf32(pw1));
            sw.z = __uint_as_float(f2tf32(pw2));   sw.w = __uint_as_float(f2tf32(pw3));
            *(float4*)&As[ar * SA + akq]        = s0;
            *(float4*)&As[(64 + ar) * SA + akq] = s1;
            *(float4*)&Ws[wnx * SW + wkg]       = sw;
            __syncthreads();
        }
    }

#pragma unroll
    for (int i = 0; i < 2; ++i) {
        const int r = row0 + wm * 32 + i * 16 + (lane >> 2);
#pragma unroll
        for (int j = 0; j < 4; ++j) {
            const int c = col0 + wn * 32 + j * 8 + ((lane & 3) << 1);
            const float b0 = __ldg(&bias[c]);
            const float b1 = __ldg(&bias[c + 1]);
            float2 v0, v1;
            v0.x = acc[i][j][0] + b0; v0.y = acc[i][j][1] + b1;
            v1.x = acc[i][j][2] + b0; v1.y = acc[i][j][3] + b1;
            *(float2*)&C[(size_t)r * N + c]       = v0;
            *(float2*)&C[(size_t)(r + 8) * N + c] = v1;
        }
    }
}

// ---------------- TF32 tensor-core flash attention ---------------------------
// 128 threads / 4 warps. Warp owns 32 q-rows (2 x m16 tiles). BC=64 keys/tile.
// k-dim permutation pi(j)=2j, pi(j+4)=2j+1 on both QK and PV mmas:
//  - K/V frags are contiguous float2 -> canonical smem layout, LDS.64 stride-1
//  - S C-frag (cols 2j,2j+1) IS the P A-frag: register rename only.
#define FBR 128
#define FBC 64

__global__ __launch_bounds__(128)
void flash_attn_tc_kernel(const float* __restrict__ Q,
                          const float* __restrict__ Km,
                          const float* __restrict__ V,
                          float* __restrict__ O)
{
    // canonical frag buffers: [kk 8][t 8][lane 32] of (tf32,tf32)
    __shared__ uint2 kfrag[8 * 8 * 32];   // 16 KB
    __shared__ uint2 vfrag[8 * 8 * 32];   // 16 KB

    const int tid  = threadIdx.x;
    const int lane = tid & 31;
    const int warp = tid >> 5;
    const int g    = lane >> 2;      // groupID (row within m8)
    const int j    = lane & 3;

    const int q0 = blockIdx.x * FBR;
    const int bh = blockIdx.y;
    const int b  = bh >> 4;
    const int h  = bh & 15;
    const size_t base = (size_t)b * SEQ * D_MODEL + (size_t)h * HEAD_DIM;

    const float c1 = 0.18033688011112042f;  // (1/sqrt(64)) * log2(e), folded into Q

    // ---- Q frags in registers, pre-scaled by c1, tf32 ----
    uint32_t qf[2][8][4];
#pragma unroll
    for (int m = 0; m < 2; ++m) {
        const int row = q0 + warp * 32 + m * 16 + g;
        const float* qp = Q + base + (size_t)row * D_MODEL;
#pragma unroll
        for (int kk = 0; kk < 8; ++kk) {
            float2 lo = *(const float2*)&qp[kk * 8 + 2 * j];
            float2 hi = *(const float2*)&qp[(size_t)8 * D_MODEL + kk * 8 + 2 * j];
            qf[m][kk][0] = f2tf32(lo.x * c1);
            qf[m][kk][2] = f2tf32(lo.y * c1);
            qf[m][kk][1] = f2tf32(hi.x * c1);
            qf[m][kk][3] = f2tf32(hi.y * c1);
        }
    }

    float accO[2][8][4];
#pragma unroll
    for (int m = 0; m < 2; ++m)
#pragma unroll
        for (int t = 0; t < 8; ++t)
#pragma unroll
            for (int e = 0; e < 4; ++e) accO[m][t][e] = 0.f;

    float mrun[2][2] = {{-1e30f, -1e30f}, {-1e30f, -1e30f}};
    float lrun[2][2] = {{0.f, 0.f}, {0.f, 0.f}};

    for (int k0 = 0; k0 < SEQ; k0 += FBC) {
        __syncthreads();   // protect previous tile's frag reads
        // ---- cooperative canonical-frag load of K and V (tf32-converted) ----
#pragma unroll
        for (int i = 0; i < 16; ++i) {
            const int f  = tid + i * 128;
            const int kk = f >> 8;
            const int tt = (f >> 5) & 7;
            const int ln = f & 31;
            const int jj = ln & 3;
            const int gg = ln >> 2;
            // K frag: key = k0 + tt*8 + gg, d = kk*8 + 2jj (+1)
            {
                const float* kp = Km + base + (size_t)(k0 + tt * 8 + gg) * D_MODEL
                                  + kk * 8 + 2 * jj;
                float2 v = *(const float2*)kp;
                kfrag[f] = make_uint2(f2tf32(v.x), f2tf32(v.y));
            }
            // V frag: keys k0 + kk*8 + 2jj (+1), d = tt*8 + gg
            {
                const size_t off = base + (size_t)(k0 + kk * 8 + 2 * jj) * D_MODEL
                                   + tt * 8 + gg;
                float v0 = __ldg(V + off);
                float v1 = __ldg(V + off + D_MODEL);
                vfrag[f] = make_uint2(f2tf32(v0), f2tf32(v1));
            }
        }
        __syncthreads();

        // ---- S = (Q*c1) @ K^T ----
        float accS[2][8][4];
#pragma unroll
        for (int m = 0; m < 2; ++m)
#pragma unroll
            for (int t = 0; t < 8; ++t)
#pragma unroll
                for (int e = 0; e < 4; ++e) accS[m][t][e] = 0.f;

#pragma unroll
        for (int t = 0; t < 8; ++t) {
#pragma unroll
            for (int kk = 0; kk < 8; ++kk) {
                uint2 kb = kfrag[(kk * 8 + t) * 32 + lane];
#pragma unroll
                for (int m = 0; m < 2; ++m) {
                    MMA_TF32(accS[m][t][0], accS[m][t][1], accS[m][t][2], accS[m][t][3],
                             qf[m][kk][0], qf[m][kk][1], qf[m][kk][2], qf[m][kk][3],
                             kb.x, kb.y);
                }
            }
        }

        // ---- online softmax (base-2; scores already scaled by c1) ----
#pragma unroll
        for (int m = 0; m < 2; ++m) {
#pragma unroll
            for (int hh = 0; hh < 2; ++hh) {
                const int e0 = 2 * hh;       // c-regs {0,1} row g ; {2,3} row g+8
                float lm = -1e30f;
#pragma unroll
                for (int t = 0; t < 8; ++t)
                    lm = fmaxf(lm, fmaxf(accS[m][t][e0], accS[m][t][e0 + 1]));
                lm = fmaxf(lm, __shfl_xor_sync(0xffffffffu, lm, 1));
                lm = fmaxf(lm, __shfl_xor_sync(0xffffffffu, lm, 2));
                const float mnew = fmaxf(mrun[m][hh], lm);
                const float corr = ex2(mrun[m][hh] - mnew);
                mrun[m][hh] = mnew;
                float ls = 0.f;
#pragma unroll
                for (int t = 0; t < 8; ++t) {
                    float p0 = ex2(accS[m][t][e0]     - mnew);
                    float p1 = ex2(accS[m][t][e0 + 1] - mnew);
                    accS[m][t][e0]     = p0;
                    accS[m][t][e0 + 1] = p1;
                    ls += p0 + p1;
                }
                ls += __shfl_xor_sync(0xffffffffu, ls, 1);
                ls += __shfl_xor_sync(0xffffffffu, ls, 2);
                lrun[m][hh] = lrun[m][hh] * corr + ls;
#pragma unroll
                for (int t = 0; t < 8; ++t) {
                    accO[m][t][e0]     *= corr;
                    accO[m][t][e0 + 1] *= corr;
                }
            }
        }

        // ---- O += P @ V  (P A-frag = S C-frag rename: a={c0,c2,c1,c3}) ----
#pragma unroll
        for (int kk = 0; kk < 8; ++kk) {
            uint32_t pf[2][4];
#pragma unroll
            for (int m = 0; m < 2; ++m) {
                pf[m][0] = f2tf32(accS[m][kk][0]);
                pf[m][1] = f2tf32(accS[m][kk][2]);
                pf[m][2] = f2tf32(accS[m][kk][1]);
                pf[m][3] = f2tf32(accS[m][kk][3]);
            }
#pragma unroll
            for (int t = 0; t < 8; ++t) {
                uint2 vb = vfrag[(kk * 8 + t) * 32 + lane];
#pragma unroll
                for (int m = 0; m < 2; ++m) {
                    MMA_TF32(accO[m][t][0], accO[m][t][1], accO[m][t][2], accO[m][t][3],
                             pf[m][0], pf[m][1], pf[m][2], pf[m][3],
                             vb.x, vb.y);
                }
            }
        }
    }

    // ---- epilogue: O /= l, store ----
#pragma unroll
    for (int m = 0; m < 2; ++m) {
        const int row = q0 + warp * 32 + m * 16 + g;
        const float inv0 = 1.f / lrun[m][0];
        const float inv1 = 1.f / lrun[m][1];
        float* op0 = O + base + (size_t)row * D_MODEL;
        float* op1 = op0 + (size_t)8 * D_MODEL;
#pragma unroll
        for (int t = 0; t < 8; ++t) {
            const int c = t * 8 + 2 * j;
            float2 v0, v1;
            v0.x = accO[m][t][0] * inv0; v0.y = accO[m][t][1] * inv0;
            v1.x = accO[m][t][2] * inv1; v1.y = accO[m][t][3] * inv1;
            *(float2*)&op0[c] = v0;
            *(float2*)&op1[c] = v1;
        }
    }
}

// ---------------- launch ----------------------------------------------------
extern "C" void kernel_launch(void* const* d_in, const int* in_sizes, int n_in,
                              void* d_out, int out_size)
{
    const float* query = (const float*)d_in[0];
    const float* key   = (const float*)d_in[1];
    const float* value = (const float*)d_in[2];
    const float* Wq    = (const float*)d_in[3];
    const float* bq    = (const float*)d_in[4];
    const float* Wk    = (const float*)d_in[5];
    const float* bk    = (const float*)d_in[6];
    const float* Wv    = (const float*)d_in[7];
    const float* bv    = (const float*)d_in[8];
    const float* Wo    = (const float*)d_in[9];
    const float* bo    = (const float*)d_in[10];
    float* out = (float*)d_out;

    float *pq, *pk, *pv, *pa;
    cudaGetSymbolAddress((void**)&pq, g_q);
    cudaGetSymbolAddress((void**)&pk, g_k);
    cudaGetSymbolAddress((void**)&pv, g_v);
    cudaGetSymbolAddress((void**)&pa, g_attn);

    dim3 gblk(D_MODEL / GBN, MTOT / GBM);   // 16 x 64
    dim3 gthr(256);

    gemm_tf32_kernel<<<gblk, gthr>>>(query, Wq, bq, pq, MTOT, D_MODEL, D_MODEL);
    gemm_tf32_kernel<<<gblk, gthr>>>(key,   Wk, bk, pk, MTOT, D_MODEL, D_MODEL);
    gemm_tf32_kernel<<<gblk, gthr>>>(value, Wv, bv, pv, MTOT, D_MODEL, D_MODEL);

    dim3 ablk(SEQ / FBR, BATCH * NUM_HEADS);  // 16 x 64
    flash_attn_tc_kernel<<<ablk, 128>>>(pq, pk, pv, pa);

    gemm_tf32_kernel<<<gblk, gthr>>>(pa, Wo, bo, out, MTOT, D_MODEL, D_MODEL);
}